// round 4
// baseline (speedup 1.0000x reference)
#include <cuda_runtime.h>
#include <cuda_bf16.h>
#include <cstdint>

// Problem constants
#define EDIM 1024
#define BATCH 2
#define SEQ 2048
#define NHEADS 16
#define HDIM 64
#define MROWS (BATCH * SEQ)          // 4096
#define QSCALE 0.125f                // 1/sqrt(64), exact power of two

// ---------------------------------------------------------------------------
// Scratch (allocation-free: static __device__ globals)
// Q/K/V live pre-split as bf16 hi/lo; O is fp32 (consumed with fused split).
// ---------------------------------------------------------------------------
__device__ __nv_bfloat16 g_Qhi[MROWS * EDIM];
__device__ __nv_bfloat16 g_Qlo[MROWS * EDIM];
__device__ __nv_bfloat16 g_Khi[MROWS * EDIM];
__device__ __nv_bfloat16 g_Klo[MROWS * EDIM];
__device__ __nv_bfloat16 g_Vhi[MROWS * EDIM];
__device__ __nv_bfloat16 g_Vlo[MROWS * EDIM];
__device__ float g_O[MROWS * EDIM];

// ---------------------------------------------------------------------------
// HMMA / ldmatrix primitives (portable sm_80+ ISA, works at compute_103)
// ---------------------------------------------------------------------------
__device__ __forceinline__ uint32_t smem_u32(const void* p) {
    uint32_t a;
    asm("{ .reg .u64 t; cvta.to.shared.u64 t, %1; cvt.u32.u64 %0, t; }"
        : "=r"(a) : "l"(p));
    return a;
}

#define LDSM_X4(r0, r1, r2, r3, addr) \
    asm volatile("ldmatrix.sync.aligned.m8n8.x4.shared.b16 {%0,%1,%2,%3}, [%4];" \
        : "=r"(r0), "=r"(r1), "=r"(r2), "=r"(r3) : "r"(addr))

#define LDSM_X4T(r0, r1, r2, r3, addr) \
    asm volatile("ldmatrix.sync.aligned.m8n8.x4.trans.shared.b16 {%0,%1,%2,%3}, [%4];" \
        : "=r"(r0), "=r"(r1), "=r"(r2), "=r"(r3) : "r"(addr))

__device__ __forceinline__ void mma_bf16(float* c, uint32_t a0, uint32_t a1,
                                         uint32_t a2, uint32_t a3,
                                         uint32_t b0, uint32_t b1) {
    asm volatile(
        "mma.sync.aligned.m16n8k16.row.col.f32.bf16.bf16.f32 "
        "{%0,%1,%2,%3}, {%4,%5,%6,%7}, {%8,%9}, {%0,%1,%2,%3};"
        : "+f"(c[0]), "+f"(c[1]), "+f"(c[2]), "+f"(c[3])
        : "r"(a0), "r"(a1), "r"(a2), "r"(a3), "r"(b0), "r"(b1));
}

__device__ __forceinline__ uint32_t pack_bf16(float x, float y) {
    __nv_bfloat162 t = __floats2bfloat162_rn(x, y);
    return *(uint32_t*)&t;
}

// Split (x,y) into bf16 hi pair + bf16 lo (residual) pair, packed.
__device__ __forceinline__ void split_pack2(float x, float y,
                                            uint32_t& hi, uint32_t& lo) {
    __nv_bfloat16 hx = __float2bfloat16(x);
    __nv_bfloat16 hy = __float2bfloat16(y);
    __nv_bfloat162 h2 = __halves2bfloat162(hx, hy);
    hi = *(uint32_t*)&h2;
    lo = pack_bf16(x - __bfloat162float(hx), y - __bfloat162float(hy));
}

// ---------------------------------------------------------------------------
// HMMA bf16x3 GEMM with FUSED input split:
//   C[M,N] = A Wt  computed as  Ahi Whi^T + Alo Whi^T + Ahi Wlo^T
// A, W read as fp32 and split during smem store.
// Epilogue: either fp32 C, or pre-split bf16 (Chi, Clo) scaled by `scale`.
// CTA 128x128, BK=64, 256 threads = 8 warps, warp tile 64x32.
// ---------------------------------------------------------------------------
#define GPAD 72
#define GTILE_HALVES (128 * GPAD)
#define GSMEM_BYTES (4 * GTILE_HALVES * 2)

__device__ __forceinline__ void gload_split(
    const float* __restrict__ g, int row0, int K, int k0,
    __nv_bfloat16* __restrict__ shi, __nv_bfloat16* __restrict__ slo, int tid)
{
#pragma unroll
    for (int it = 0; it < 8; it++) {
        int l = it * 256 + tid;      // 0..2047
        int r = l >> 4;              // 0..127
        int c = (l & 15) * 4;        // 0..60
        float4 v = *(const float4*)(g + (size_t)(row0 + r) * K + k0 + c);
        uint32_t h01, l01, h23, l23;
        split_pack2(v.x, v.y, h01, l01);
        split_pack2(v.z, v.w, h23, l23);
        *(uint2*)(shi + r * GPAD + c) = make_uint2(h01, h23);
        *(uint2*)(slo + r * GPAD + c) = make_uint2(l01, l23);
    }
}

__global__ __launch_bounds__(256) void hgemm_f32in(
    const float* __restrict__ A, const float* __restrict__ W,
    float* __restrict__ Cf,
    __nv_bfloat16* __restrict__ Chi, __nv_bfloat16* __restrict__ Clo,
    float scale, int M, int N, int K)
{
    extern __shared__ __nv_bfloat16 hsm[];
    __nv_bfloat16* sAhi = hsm;
    __nv_bfloat16* sAlo = hsm + GTILE_HALVES;
    __nv_bfloat16* sWhi = hsm + 2 * GTILE_HALVES;
    __nv_bfloat16* sWlo = hsm + 3 * GTILE_HALVES;

    const int tid = threadIdx.x;
    const int wid = tid >> 5;
    const int lane = tid & 31;
    const int bm = blockIdx.y * 128;
    const int bn = blockIdx.x * 128;
    const int moff = (wid >> 2) * 64;   // 0 or 64
    const int noff = (wid & 3) * 32;    // 0..96

    float acc[4][4][4];
#pragma unroll
    for (int mt = 0; mt < 4; mt++)
#pragma unroll
        for (int nt = 0; nt < 4; nt++)
#pragma unroll
            for (int r = 0; r < 4; r++) acc[mt][nt][r] = 0.f;

    const uint32_t aHiB = smem_u32(sAhi);
    const uint32_t aLoB = smem_u32(sAlo);
    const uint32_t wHiB = smem_u32(sWhi);
    const uint32_t wLoB = smem_u32(sWlo);

    // ldmatrix per-thread byte offsets
    const uint32_t a_off = ((moff + (lane & 15)) * GPAD + (lane >> 4) * 8) * 2;
    // X4 B: two adjacent 8-col n-blocks per load
    const uint32_t b4_off =
        ((noff + ((lane >> 4) & 1) * 8 + (lane & 7)) * GPAD + ((lane >> 3) & 1) * 8) * 2;

    for (int t = 0; t < K / 64; t++) {
        __syncthreads();
        const int k0 = t * 64;
        gload_split(A, bm, K, k0, sAhi, sAlo, tid);
        gload_split(W, bn, K, k0, sWhi, sWlo, tid);
        __syncthreads();

#pragma unroll
        for (int ks = 0; ks < 4; ks++) {
            const uint32_t koff = ks * 32;
            uint32_t bhi[4][2], blo[4][2];
#pragma unroll
            for (int ntp = 0; ntp < 2; ntp++) {
                const uint32_t boff = b4_off + ntp * (16 * GPAD * 2) + koff;
                LDSM_X4(bhi[2 * ntp][0], bhi[2 * ntp][1],
                        bhi[2 * ntp + 1][0], bhi[2 * ntp + 1][1], wHiB + boff);
                LDSM_X4(blo[2 * ntp][0], blo[2 * ntp][1],
                        blo[2 * ntp + 1][0], blo[2 * ntp + 1][1], wLoB + boff);
            }
#pragma unroll
            for (int mt = 0; mt < 4; mt++) {
                uint32_t ah0, ah1, ah2, ah3, al0, al1, al2, al3;
                LDSM_X4(ah0, ah1, ah2, ah3, aHiB + a_off + mt * (16 * GPAD * 2) + koff);
                LDSM_X4(al0, al1, al2, al3, aLoB + a_off + mt * (16 * GPAD * 2) + koff);
#pragma unroll
                for (int nt = 0; nt < 4; nt++) {
                    mma_bf16(acc[mt][nt], ah0, ah1, ah2, ah3, bhi[nt][0], bhi[nt][1]);
                    mma_bf16(acc[mt][nt], al0, al1, al2, al3, bhi[nt][0], bhi[nt][1]);
                    mma_bf16(acc[mt][nt], ah0, ah1, ah2, ah3, blo[nt][0], blo[nt][1]);
                }
            }
        }
    }

    // Epilogue
    if (Cf) {
#pragma unroll
        for (int mt = 0; mt < 4; mt++)
#pragma unroll
            for (int nt = 0; nt < 4; nt++) {
                int r0 = bm + moff + mt * 16 + (lane >> 2);
                int c0 = bn + noff + nt * 8 + (lane & 3) * 2;
                *(float2*)(Cf + (size_t)r0 * N + c0) = make_float2(acc[mt][nt][0], acc[mt][nt][1]);
                *(float2*)(Cf + (size_t)(r0 + 8) * N + c0) = make_float2(acc[mt][nt][2], acc[mt][nt][3]);
            }
    } else {
#pragma unroll
        for (int mt = 0; mt < 4; mt++)
#pragma unroll
            for (int nt = 0; nt < 4; nt++) {
                int r0 = bm + moff + mt * 16 + (lane >> 2);
                int c0 = bn + noff + nt * 8 + (lane & 3) * 2;
                uint32_t h, l;
                split_pack2(acc[mt][nt][0] * scale, acc[mt][nt][1] * scale, h, l);
                *(uint32_t*)(Chi + (size_t)r0 * N + c0) = h;
                *(uint32_t*)(Clo + (size_t)r0 * N + c0) = l;
                split_pack2(acc[mt][nt][2] * scale, acc[mt][nt][3] * scale, h, l);
                *(uint32_t*)(Chi + (size_t)(r0 + 8) * N + c0) = h;
                *(uint32_t*)(Clo + (size_t)(r0 + 8) * N + c0) = l;
            }
    }
}

// ---------------------------------------------------------------------------
// Flash attention on HMMA. Inputs pre-split bf16 hi/lo (Q pre-scaled).
// CTA: 128 q-rows of one (b,h); 8 warps; warp = 16 q-rows x 128-kv tile.
// ---------------------------------------------------------------------------
#define FPAD 72
#define FTILE_HALVES (128 * FPAD)
#define FSMEM_BYTES (6 * FTILE_HALVES * 2)

__device__ __forceinline__ void fload_bf16(
    const __nv_bfloat16* __restrict__ g, __nv_bfloat16* __restrict__ s, int tid)
{
#pragma unroll
    for (int it = 0; it < 4; it++) {
        int l = it * 256 + tid;   // 0..1023 chunks of 8 halves
        int r = l >> 3;
        int c = (l & 7) * 8;
        *(uint4*)(s + r * FPAD + c) = *(const uint4*)(g + (size_t)r * EDIM + c);
    }
}

__global__ __launch_bounds__(256) void flash_hmma()
{
    extern __shared__ __nv_bfloat16 fsm[];
    __nv_bfloat16* sQhi = fsm;
    __nv_bfloat16* sQlo = fsm + FTILE_HALVES;
    __nv_bfloat16* sKhi = fsm + 2 * FTILE_HALVES;
    __nv_bfloat16* sKlo = fsm + 3 * FTILE_HALVES;
    __nv_bfloat16* sVhi = fsm + 4 * FTILE_HALVES;
    __nv_bfloat16* sVlo = fsm + 5 * FTILE_HALVES;

    const int tid = threadIdx.x;
    const int wid = tid >> 5;
    const int lane = tid & 31;
    const int qb = blockIdx.x * 128;
    const int h = blockIdx.y;
    const int b = blockIdx.z;

    const size_t qbase = ((size_t)b * SEQ + qb) * EDIM + h * HDIM;
    const size_t kvbase = (size_t)b * SEQ * EDIM + h * HDIM;

    fload_bf16(g_Qhi + qbase, sQhi, tid);
    fload_bf16(g_Qlo + qbase, sQlo, tid);
    __syncthreads();

    const uint32_t qHiB = smem_u32(sQhi);
    const uint32_t qLoB = smem_u32(sQlo);
    const uint32_t kHiB = smem_u32(sKhi);
    const uint32_t kLoB = smem_u32(sKlo);
    const uint32_t vHiB = smem_u32(sVhi);
    const uint32_t vLoB = smem_u32(sVlo);

    // ldmatrix per-thread byte offsets
    const uint32_t a_off = ((wid * 16 + (lane & 15)) * FPAD + (lane >> 4) * 8) * 2;
    const uint32_t k4_off =
        ((((lane >> 4) & 1) * 8 + (lane & 7)) * FPAD + ((lane >> 3) & 1) * 8) * 2;
    const uint32_t v4_off =
        (((lane & 7) + ((lane >> 3) & 1) * 8) * FPAD + ((lane >> 4) & 1) * 8) * 2;

    float o[8][4];
#pragma unroll
    for (int nt = 0; nt < 8; nt++)
#pragma unroll
        for (int r = 0; r < 4; r++) o[nt][r] = 0.f;
    float m0 = -1e30f, m1 = -1e30f, l0 = 0.f, l1 = 0.f;

    for (int kb = 0; kb < SEQ; kb += 128) {
        __syncthreads();
        const size_t kvo = kvbase + (size_t)kb * EDIM;
        fload_bf16(g_Khi + kvo, sKhi, tid);
        fload_bf16(g_Klo + kvo, sKlo, tid);
        fload_bf16(g_Vhi + kvo, sVhi, tid);
        fload_bf16(g_Vlo + kvo, sVlo, tid);
        __syncthreads();

        // --- S = Qhi Khi^T + Qlo Khi^T + Qhi Klo^T ---
        float s[16][4];
#pragma unroll
        for (int nt = 0; nt < 16; nt++)
#pragma unroll
            for (int r = 0; r < 4; r++) s[nt][r] = 0.f;

#pragma unroll
        for (int ks = 0; ks < 4; ks++) {
            const uint32_t koff = ks * 32;
            uint32_t qh0, qh1, qh2, qh3, ql0, ql1, ql2, ql3;
            LDSM_X4(qh0, qh1, qh2, qh3, qHiB + a_off + koff);
            LDSM_X4(ql0, ql1, ql2, ql3, qLoB + a_off + koff);
#pragma unroll
            for (int ntp = 0; ntp < 8; ntp++) {
                const uint32_t boff = k4_off + ntp * (16 * FPAD * 2) + koff;
                uint32_t h0, h1, h2, h3;
                LDSM_X4(h0, h1, h2, h3, kHiB + boff);
                mma_bf16(s[2 * ntp],     qh0, qh1, qh2, qh3, h0, h1);
                mma_bf16(s[2 * ntp + 1], qh0, qh1, qh2, qh3, h2, h3);
                mma_bf16(s[2 * ntp],     ql0, ql1, ql2, ql3, h0, h1);
                mma_bf16(s[2 * ntp + 1], ql0, ql1, ql2, ql3, h2, h3);
                uint32_t e0, e1, e2, e3;
                LDSM_X4(e0, e1, e2, e3, kLoB + boff);
                mma_bf16(s[2 * ntp],     qh0, qh1, qh2, qh3, e0, e1);
                mma_bf16(s[2 * ntp + 1], qh0, qh1, qh2, qh3, e2, e3);
            }
        }

        // --- online softmax (rows r0 = regs 0,1 ; r1 = regs 2,3) ---
        float mx0 = -1e30f, mx1 = -1e30f;
#pragma unroll
        for (int nt = 0; nt < 16; nt++) {
            mx0 = fmaxf(mx0, fmaxf(s[nt][0], s[nt][1]));
            mx1 = fmaxf(mx1, fmaxf(s[nt][2], s[nt][3]));
        }
        mx0 = fmaxf(mx0, __shfl_xor_sync(0xffffffffu, mx0, 1));
        mx0 = fmaxf(mx0, __shfl_xor_sync(0xffffffffu, mx0, 2));
        mx1 = fmaxf(mx1, __shfl_xor_sync(0xffffffffu, mx1, 1));
        mx1 = fmaxf(mx1, __shfl_xor_sync(0xffffffffu, mx1, 2));

        float mn0 = fmaxf(m0, mx0), mn1 = fmaxf(m1, mx1);
        float al0 = __expf(m0 - mn0), al1 = __expf(m1 - mn1);
        m0 = mn0; m1 = mn1;

        float sum0 = 0.f, sum1 = 0.f;
#pragma unroll
        for (int nt = 0; nt < 16; nt++) {
            s[nt][0] = __expf(s[nt][0] - mn0);
            s[nt][1] = __expf(s[nt][1] - mn0);
            s[nt][2] = __expf(s[nt][2] - mn1);
            s[nt][3] = __expf(s[nt][3] - mn1);
            sum0 += s[nt][0] + s[nt][1];
            sum1 += s[nt][2] + s[nt][3];
        }
        sum0 += __shfl_xor_sync(0xffffffffu, sum0, 1);
        sum0 += __shfl_xor_sync(0xffffffffu, sum0, 2);
        sum1 += __shfl_xor_sync(0xffffffffu, sum1, 1);
        sum1 += __shfl_xor_sync(0xffffffffu, sum1, 2);
        l0 = l0 * al0 + sum0;
        l1 = l1 * al1 + sum1;

#pragma unroll
        for (int nt = 0; nt < 8; nt++) {
            o[nt][0] *= al0; o[nt][1] *= al0;
            o[nt][2] *= al1; o[nt][3] *= al1;
        }

        // --- O += Phi Vhi + Plo Vhi + Phi Vlo ---
#pragma unroll
        for (int kt = 0; kt < 8; kt++) {
            uint32_t ph[4], pl[4];
            split_pack2(s[2 * kt][0],     s[2 * kt][1],     ph[0], pl[0]);
            split_pack2(s[2 * kt][2],     s[2 * kt][3],     ph[1], pl[1]);
            split_pack2(s[2 * kt + 1][0], s[2 * kt + 1][1], ph[2], pl[2]);
            split_pack2(s[2 * kt + 1][2], s[2 * kt + 1][3], ph[3], pl[3]);
#pragma unroll
            for (int ntp = 0; ntp < 4; ntp++) {
                const uint32_t voff = v4_off + kt * (16 * FPAD * 2) + ntp * 32;
                uint32_t vh0, vh1, vh2, vh3;
                LDSM_X4T(vh0, vh1, vh2, vh3, vHiB + voff);
                mma_bf16(o[2 * ntp],     ph[0], ph[1], ph[2], ph[3], vh0, vh1);
                mma_bf16(o[2 * ntp + 1], ph[0], ph[1], ph[2], ph[3], vh2, vh3);
                mma_bf16(o[2 * ntp],     pl[0], pl[1], pl[2], pl[3], vh0, vh1);
                mma_bf16(o[2 * ntp + 1], pl[0], pl[1], pl[2], pl[3], vh2, vh3);
                uint32_t vl0, vl1, vl2, vl3;
                LDSM_X4T(vl0, vl1, vl2, vl3, vLoB + voff);
                mma_bf16(o[2 * ntp],     ph[0], ph[1], ph[2], ph[3], vl0, vl1);
                mma_bf16(o[2 * ntp + 1], ph[0], ph[1], ph[2], ph[3], vl2, vl3);
            }
        }
    }

    // Epilogue: normalize, store fp32
    const int r0 = qb + wid * 16 + (lane >> 2);
    float inv0 = 1.f / l0, inv1 = 1.f / l1;
    float* Orow = g_O + ((size_t)b * SEQ + r0) * EDIM + h * HDIM;
#pragma unroll
    for (int nt = 0; nt < 8; nt++) {
        int c = nt * 8 + (lane & 3) * 2;
        *(float2*)(Orow + c) = make_float2(o[nt][0] * inv0, o[nt][1] * inv0);
        *(float2*)(Orow + (size_t)8 * EDIM + c) = make_float2(o[nt][2] * inv1, o[nt][3] * inv1);
    }
}

// ---------------------------------------------------------------------------
// Launch: 5 kernels total (3 proj GEMMs, flash, out GEMM)
// ---------------------------------------------------------------------------
extern "C" void kernel_launch(void* const* d_in, const int* in_sizes, int n_in,
                              void* d_out, int out_size)
{
    (void)in_sizes; (void)n_in; (void)out_size;
    const float* q  = (const float*)d_in[0];
    const float* k  = (const float*)d_in[1];
    const float* v  = (const float*)d_in[2];
    const float* Wq = (const float*)d_in[3];
    const float* Wk = (const float*)d_in[4];
    const float* Wv = (const float*)d_in[5];
    const float* Wo = (const float*)d_in[6];
    float* out = (float*)d_out;

    __nv_bfloat16 *Qhi, *Qlo, *Khi, *Klo, *Vhi, *Vlo;
    float* Op;
    cudaGetSymbolAddress((void**)&Qhi, g_Qhi);
    cudaGetSymbolAddress((void**)&Qlo, g_Qlo);
    cudaGetSymbolAddress((void**)&Khi, g_Khi);
    cudaGetSymbolAddress((void**)&Klo, g_Klo);
    cudaGetSymbolAddress((void**)&Vhi, g_Vhi);
    cudaGetSymbolAddress((void**)&Vlo, g_Vlo);
    cudaGetSymbolAddress((void**)&Op, g_O);

    static int attr_set = 0;
    if (!attr_set) {
        cudaFuncSetAttribute(hgemm_f32in,
                             cudaFuncAttributeMaxDynamicSharedMemorySize, GSMEM_BYTES);
        cudaFuncSetAttribute(flash_hmma,
                             cudaFuncAttributeMaxDynamicSharedMemorySize, FSMEM_BYTES);
        attr_set = 1;
    }

    dim3 ggrid(EDIM / 128, MROWS / 128);   // (8, 32)

    // Projections (epilogue writes pre-split bf16; Q pre-scaled by 1/sqrt(D))
    hgemm_f32in<<<ggrid, 256, GSMEM_BYTES>>>(q, Wq, nullptr, Qhi, Qlo, QSCALE, MROWS, EDIM, EDIM);
    hgemm_f32in<<<ggrid, 256, GSMEM_BYTES>>>(k, Wk, nullptr, Khi, Klo, 1.0f,   MROWS, EDIM, EDIM);
    hgemm_f32in<<<ggrid, 256, GSMEM_BYTES>>>(v, Wv, nullptr, Vhi, Vlo, 1.0f,   MROWS, EDIM, EDIM);

    // Fused flash attention
    dim3 fgrid(SEQ / 128, NHEADS, BATCH);  // (16, 16, 2)
    flash_hmma<<<fgrid, 256, FSMEM_BYTES>>>();

    // Output projection (fp32 in via fused split, fp32 out)
    hgemm_f32in<<<ggrid, 256, GSMEM_BYTES>>>(Op, Wo, out, nullptr, nullptr, 1.0f, MROWS, EDIM, EDIM);
}

// round 5
// speedup vs baseline: 1.1511x; 1.1511x over previous
#include <cuda_runtime.h>
#include <cuda_bf16.h>
#include <cstdint>

// Problem constants
#define EDIM 1024
#define BATCH 2
#define SEQ 2048
#define NHEADS 16
#define HDIM 64
#define MROWS (BATCH * SEQ)          // 4096
#define QSCALE 0.125f                // 1/sqrt(64), exact power of two

// ---------------------------------------------------------------------------
// Scratch (allocation-free: static __device__ globals)
// ---------------------------------------------------------------------------
__device__ __nv_bfloat16 g_Qhi[MROWS * EDIM];
__device__ __nv_bfloat16 g_Qlo[MROWS * EDIM];
__device__ __nv_bfloat16 g_Khi[MROWS * EDIM];
__device__ __nv_bfloat16 g_Klo[MROWS * EDIM];
__device__ __nv_bfloat16 g_Vhi[MROWS * EDIM];
__device__ __nv_bfloat16 g_Vlo[MROWS * EDIM];
__device__ float g_O[MROWS * EDIM];
__device__ __nv_bfloat16 g_ahi[MROWS * EDIM];   // activation split scratch
__device__ __nv_bfloat16 g_alo[MROWS * EDIM];
__device__ __nv_bfloat16 g_whi[EDIM * EDIM];    // weight split scratch
__device__ __nv_bfloat16 g_wlo[EDIM * EDIM];

// ---------------------------------------------------------------------------
// Primitives
// ---------------------------------------------------------------------------
__device__ __forceinline__ uint32_t smem_u32(const void* p) {
    uint32_t a;
    asm("{ .reg .u64 t; cvta.to.shared.u64 t, %1; cvt.u32.u64 %0, t; }"
        : "=r"(a) : "l"(p));
    return a;
}

#define LDSM_X4(r0, r1, r2, r3, addr) \
    asm volatile("ldmatrix.sync.aligned.m8n8.x4.shared.b16 {%0,%1,%2,%3}, [%4];" \
        : "=r"(r0), "=r"(r1), "=r"(r2), "=r"(r3) : "r"(addr))

#define LDSM_X4T(r0, r1, r2, r3, addr) \
    asm volatile("ldmatrix.sync.aligned.m8n8.x4.trans.shared.b16 {%0,%1,%2,%3}, [%4];" \
        : "=r"(r0), "=r"(r1), "=r"(r2), "=r"(r3) : "r"(addr))

#define CP_ASYNC16(saddr, gptr) \
    asm volatile("cp.async.cg.shared.global [%0], [%1], 16;" \
        :: "r"(saddr), "l"(gptr))

#define CP_COMMIT() asm volatile("cp.async.commit_group;" ::: "memory")
#define CP_WAIT1()  asm volatile("cp.async.wait_group 1;" ::: "memory")
#define CP_WAIT0()  asm volatile("cp.async.wait_group 0;" ::: "memory")

__device__ __forceinline__ void mma_bf16(float* c, uint32_t a0, uint32_t a1,
                                         uint32_t a2, uint32_t a3,
                                         uint32_t b0, uint32_t b1) {
    asm volatile(
        "mma.sync.aligned.m16n8k16.row.col.f32.bf16.bf16.f32 "
        "{%0,%1,%2,%3}, {%4,%5,%6,%7}, {%8,%9}, {%0,%1,%2,%3};"
        : "+f"(c[0]), "+f"(c[1]), "+f"(c[2]), "+f"(c[3])
        : "r"(a0), "r"(a1), "r"(a2), "r"(a3), "r"(b0), "r"(b1));
}

__device__ __forceinline__ uint32_t pack_bf16(float x, float y) {
    __nv_bfloat162 t = __floats2bfloat162_rn(x, y);
    return *(uint32_t*)&t;
}

__device__ __forceinline__ void split_pack2(float x, float y,
                                            uint32_t& hi, uint32_t& lo) {
    __nv_bfloat16 hx = __float2bfloat16(x);
    __nv_bfloat16 hy = __float2bfloat16(y);
    __nv_bfloat162 h2 = __halves2bfloat162(hx, hy);
    hi = *(uint32_t*)&h2;
    lo = pack_bf16(x - __bfloat162float(hx), y - __bfloat162float(hy));
}

// ---------------------------------------------------------------------------
// Standalone split: fp32 -> (bf16 hi, bf16 lo)
// ---------------------------------------------------------------------------
__global__ __launch_bounds__(256) void split_bf16_kernel(
    const float* __restrict__ x,
    __nv_bfloat16* __restrict__ hi,
    __nv_bfloat16* __restrict__ lo,
    int n)
{
    int i = (blockIdx.x * blockDim.x + threadIdx.x) * 4;
    if (i >= n) return;
    float4 v = *(const float4*)(x + i);
    uint32_t h01, l01, h23, l23;
    split_pack2(v.x, v.y, h01, l01);
    split_pack2(v.z, v.w, h23, l23);
    *(uint2*)(hi + i) = make_uint2(h01, h23);
    *(uint2*)(lo + i) = make_uint2(l01, l23);
}

// ---------------------------------------------------------------------------
// Pipelined HMMA bf16x3 GEMM: C = Ahi Whi^T + Alo Whi^T + Ahi Wlo^T
// CTA 128x128, BK=32, 2-stage cp.async double buffer, 8 warps (64x32 each).
// Epilogue: fp32 C, or pre-split bf16 (Chi, Clo) scaled by `scale`.
// ---------------------------------------------------------------------------
#define GPAD 40
#define GT_BYTES (128 * GPAD * 2)        // 10240 per tile
#define GSMEM_BYTES (8 * GT_BYTES)       // 2 stages x 4 tiles = 81920

__global__ __launch_bounds__(256) void hgemm_pipe(
    const __nv_bfloat16* __restrict__ Ahi, const __nv_bfloat16* __restrict__ Alo,
    const __nv_bfloat16* __restrict__ Whi, const __nv_bfloat16* __restrict__ Wlo,
    float* __restrict__ Cf,
    __nv_bfloat16* __restrict__ Chi, __nv_bfloat16* __restrict__ Clo,
    float scale, int M, int N, int K)
{
    extern __shared__ __nv_bfloat16 hsm[];
    const uint32_t sb = smem_u32(hsm);

    const int tid = threadIdx.x;
    const int wid = tid >> 5;
    const int lane = tid & 31;
    const int bm = blockIdx.y * 128;
    const int bn = blockIdx.x * 128;
    const int moff = (wid >> 2) * 64;
    const int noff = (wid & 3) * 32;

    // load coords: 4 chunks/row of 32 halves; thread -> row (tid>>2), chunk (tid&3)
    const int lr = tid >> 2;            // 0..63
    const int lc = (tid & 3) * 8;       // 0,8,16,24
    const size_t gA0 = (size_t)(bm + lr) * K + lc;
    const size_t gW0 = (size_t)(bn + lr) * K + lc;
    const uint32_t sOff0 = (uint32_t)(lr * GPAD + lc) * 2;
    const uint32_t sOff1 = (uint32_t)((lr + 64) * GPAD + lc) * 2;

    float acc[4][4][4];
#pragma unroll
    for (int mt = 0; mt < 4; mt++)
#pragma unroll
        for (int nt = 0; nt < 4; nt++)
#pragma unroll
            for (int r = 0; r < 4; r++) acc[mt][nt][r] = 0.f;

    const uint32_t a_off = ((moff + (lane & 15)) * GPAD + (lane >> 4) * 8) * 2;
    const uint32_t b4_off =
        ((noff + ((lane >> 4) & 1) * 8 + (lane & 7)) * GPAD + ((lane >> 3) & 1) * 8) * 2;

    const int NT = K / 32;

    auto load_stage = [&](int t) {
        const int s = t & 1;
        const int k0 = t * 32;
        const uint32_t s0 = sb + s * 4 * GT_BYTES;
        const __nv_bfloat16* g;
        g = Ahi + gA0 + k0;
        CP_ASYNC16(s0 + 0 * GT_BYTES + sOff0, g);
        CP_ASYNC16(s0 + 0 * GT_BYTES + sOff1, g + (size_t)64 * K);
        g = Alo + gA0 + k0;
        CP_ASYNC16(s0 + 1 * GT_BYTES + sOff0, g);
        CP_ASYNC16(s0 + 1 * GT_BYTES + sOff1, g + (size_t)64 * K);
        g = Whi + gW0 + k0;
        CP_ASYNC16(s0 + 2 * GT_BYTES + sOff0, g);
        CP_ASYNC16(s0 + 2 * GT_BYTES + sOff1, g + (size_t)64 * K);
        g = Wlo + gW0 + k0;
        CP_ASYNC16(s0 + 3 * GT_BYTES + sOff0, g);
        CP_ASYNC16(s0 + 3 * GT_BYTES + sOff1, g + (size_t)64 * K);
    };

    load_stage(0);
    CP_COMMIT();

    for (int t = 0; t < NT; t++) {
        if (t + 1 < NT) {
            load_stage(t + 1);
            CP_COMMIT();
            CP_WAIT1();
        } else {
            CP_WAIT0();
        }
        __syncthreads();

        const uint32_t s0 = sb + (t & 1) * 4 * GT_BYTES;
        const uint32_t aHiB = s0;
        const uint32_t aLoB = s0 + GT_BYTES;
        const uint32_t wHiB = s0 + 2 * GT_BYTES;
        const uint32_t wLoB = s0 + 3 * GT_BYTES;

#pragma unroll
        for (int ks = 0; ks < 2; ks++) {
            const uint32_t koff = ks * 32;
            uint32_t bhi[4][2], blo[4][2];
#pragma unroll
            for (int ntp = 0; ntp < 2; ntp++) {
                const uint32_t boff = b4_off + ntp * (16 * GPAD * 2) + koff;
                LDSM_X4(bhi[2 * ntp][0], bhi[2 * ntp][1],
                        bhi[2 * ntp + 1][0], bhi[2 * ntp + 1][1], wHiB + boff);
                LDSM_X4(blo[2 * ntp][0], blo[2 * ntp][1],
                        blo[2 * ntp + 1][0], blo[2 * ntp + 1][1], wLoB + boff);
            }
#pragma unroll
            for (int mt = 0; mt < 4; mt++) {
                uint32_t ah0, ah1, ah2, ah3, al0, al1, al2, al3;
                LDSM_X4(ah0, ah1, ah2, ah3, aHiB + a_off + mt * (16 * GPAD * 2) + koff);
                LDSM_X4(al0, al1, al2, al3, aLoB + a_off + mt * (16 * GPAD * 2) + koff);
#pragma unroll
                for (int nt = 0; nt < 4; nt++) {
                    mma_bf16(acc[mt][nt], ah0, ah1, ah2, ah3, bhi[nt][0], bhi[nt][1]);
                    mma_bf16(acc[mt][nt], al0, al1, al2, al3, bhi[nt][0], bhi[nt][1]);
                    mma_bf16(acc[mt][nt], ah0, ah1, ah2, ah3, blo[nt][0], blo[nt][1]);
                }
            }
        }
        __syncthreads();
    }

    // Epilogue
    if (Cf) {
#pragma unroll
        for (int mt = 0; mt < 4; mt++)
#pragma unroll
            for (int nt = 0; nt < 4; nt++) {
                int r0 = bm + moff + mt * 16 + (lane >> 2);
                int c0 = bn + noff + nt * 8 + (lane & 3) * 2;
                *(float2*)(Cf + (size_t)r0 * N + c0) = make_float2(acc[mt][nt][0], acc[mt][nt][1]);
                *(float2*)(Cf + (size_t)(r0 + 8) * N + c0) = make_float2(acc[mt][nt][2], acc[mt][nt][3]);
            }
    } else {
#pragma unroll
        for (int mt = 0; mt < 4; mt++)
#pragma unroll
            for (int nt = 0; nt < 4; nt++) {
                int r0 = bm + moff + mt * 16 + (lane >> 2);
                int c0 = bn + noff + nt * 8 + (lane & 3) * 2;
                uint32_t h, l;
                split_pack2(acc[mt][nt][0] * scale, acc[mt][nt][1] * scale, h, l);
                *(uint32_t*)(Chi + (size_t)r0 * N + c0) = h;
                *(uint32_t*)(Clo + (size_t)r0 * N + c0) = l;
                split_pack2(acc[mt][nt][2] * scale, acc[mt][nt][3] * scale, h, l);
                *(uint32_t*)(Chi + (size_t)(r0 + 8) * N + c0) = h;
                *(uint32_t*)(Clo + (size_t)(r0 + 8) * N + c0) = l;
            }
    }
}

// ---------------------------------------------------------------------------
// Flash attention on HMMA, cp.async double-buffered 64-row KV stages.
// CTA: 128 q-rows of one (b,h); 8 warps; warp = 16 q-rows.
// Q fragments hoisted to registers for the whole KV loop.
// ---------------------------------------------------------------------------
#define FPAD 72
#define FQ_BYTES (128 * FPAD * 2)        // 18432 per Q tile
#define FKV_BYTES (64 * FPAD * 2)        // 9216 per KV tile
#define FSMEM_BYTES (2 * FQ_BYTES + 2 * 4 * FKV_BYTES)   // 110592

__global__ __launch_bounds__(256) void flash_hmma()
{
    extern __shared__ __nv_bfloat16 fsm[];
    const uint32_t sb = smem_u32(fsm);
    const uint32_t qHiB = sb;
    const uint32_t qLoB = sb + FQ_BYTES;
    const uint32_t kvB = sb + 2 * FQ_BYTES;   // + s*4*FKV + tile*FKV

    const int tid = threadIdx.x;
    const int wid = tid >> 5;
    const int lane = tid & 31;
    const int qb = blockIdx.x * 128;
    const int h = blockIdx.y;
    const int b = blockIdx.z;

    const size_t qbase = ((size_t)b * SEQ + qb) * EDIM + h * HDIM;
    const size_t kvbase = (size_t)b * SEQ * EDIM + h * HDIM;

    // Q tiles -> smem (regular loads, once)
#pragma unroll
    for (int it = 0; it < 4; it++) {
        int l = it * 256 + tid;
        int r = l >> 3;
        int c = (l & 7) * 8;
        *(uint4*)(fsm + (qHiB - sb) / 2 + r * FPAD + c) = *(const uint4*)(g_Qhi + qbase + (size_t)r * EDIM + c);
        *(uint4*)(fsm + (qLoB - sb) / 2 + r * FPAD + c) = *(const uint4*)(g_Qlo + qbase + (size_t)r * EDIM + c);
    }
    __syncthreads();

    // Hoist Q fragments (invariant over KV loop)
    const uint32_t a_off = ((wid * 16 + (lane & 15)) * FPAD + (lane >> 4) * 8) * 2;
    uint32_t qh[4][4], ql[4][4];
#pragma unroll
    for (int ks = 0; ks < 4; ks++) {
        LDSM_X4(qh[ks][0], qh[ks][1], qh[ks][2], qh[ks][3], qHiB + a_off + ks * 32);
        LDSM_X4(ql[ks][0], ql[ks][1], ql[ks][2], ql[ks][3], qLoB + a_off + ks * 32);
    }

    // KV stage loaders: 2 chunks per tile per thread
    const int lr = tid >> 3;            // 0..31
    const int lc = (tid & 7) * 8;       // 0..56
    const size_t gKV0 = kvbase + (size_t)lr * EDIM + lc;
    const uint32_t sKV0 = (uint32_t)(lr * FPAD + lc) * 2;
    const uint32_t sKV1 = (uint32_t)((lr + 32) * FPAD + lc) * 2;

    auto load_stage = [&](int t) {
        const uint32_t s0 = kvB + (t & 1) * 4 * FKV_BYTES;
        const size_t g0 = gKV0 + (size_t)t * 64 * EDIM;
        CP_ASYNC16(s0 + 0 * FKV_BYTES + sKV0, g_Khi + g0);
        CP_ASYNC16(s0 + 0 * FKV_BYTES + sKV1, g_Khi + g0 + (size_t)32 * EDIM);
        CP_ASYNC16(s0 + 1 * FKV_BYTES + sKV0, g_Klo + g0);
        CP_ASYNC16(s0 + 1 * FKV_BYTES + sKV1, g_Klo + g0 + (size_t)32 * EDIM);
        CP_ASYNC16(s0 + 2 * FKV_BYTES + sKV0, g_Vhi + g0);
        CP_ASYNC16(s0 + 2 * FKV_BYTES + sKV1, g_Vhi + g0 + (size_t)32 * EDIM);
        CP_ASYNC16(s0 + 3 * FKV_BYTES + sKV0, g_Vlo + g0);
        CP_ASYNC16(s0 + 3 * FKV_BYTES + sKV1, g_Vlo + g0 + (size_t)32 * EDIM);
    };

    const uint32_t k4_off =
        ((((lane >> 4) & 1) * 8 + (lane & 7)) * FPAD + ((lane >> 3) & 1) * 8) * 2;
    const uint32_t v4_off =
        (((lane & 7) + ((lane >> 3) & 1) * 8) * FPAD + ((lane >> 4) & 1) * 8) * 2;

    float o[8][4];
#pragma unroll
    for (int nt = 0; nt < 8; nt++)
#pragma unroll
        for (int r = 0; r < 4; r++) o[nt][r] = 0.f;
    float m0 = -1e30f, m1 = -1e30f, l0 = 0.f, l1 = 0.f;

    const int NT = SEQ / 64;   // 32
    load_stage(0);
    CP_COMMIT();

    for (int t = 0; t < NT; t++) {
        if (t + 1 < NT) {
            load_stage(t + 1);
            CP_COMMIT();
            CP_WAIT1();
        } else {
            CP_WAIT0();
        }
        __syncthreads();

        const uint32_t s0 = kvB + (t & 1) * 4 * FKV_BYTES;
        const uint32_t kHiB = s0;
        const uint32_t kLoB = s0 + FKV_BYTES;
        const uint32_t vHiB = s0 + 2 * FKV_BYTES;
        const uint32_t vLoB = s0 + 3 * FKV_BYTES;

        // --- S = Qhi Khi^T + Qlo Khi^T + Qhi Klo^T  (16 q x 64 kv per warp) ---
        float s[8][4];
#pragma unroll
        for (int nt = 0; nt < 8; nt++)
#pragma unroll
            for (int r = 0; r < 4; r++) s[nt][r] = 0.f;

#pragma unroll
        for (int ks = 0; ks < 4; ks++) {
            const uint32_t koff = ks * 32;
#pragma unroll
            for (int ntp = 0; ntp < 4; ntp++) {
                const uint32_t boff = k4_off + ntp * (16 * FPAD * 2) + koff;
                uint32_t h0, h1, h2, h3;
                LDSM_X4(h0, h1, h2, h3, kHiB + boff);
                mma_bf16(s[2 * ntp],     qh[ks][0], qh[ks][1], qh[ks][2], qh[ks][3], h0, h1);
                mma_bf16(s[2 * ntp + 1], qh[ks][0], qh[ks][1], qh[ks][2], qh[ks][3], h2, h3);
                mma_bf16(s[2 * ntp],     ql[ks][0], ql[ks][1], ql[ks][2], ql[ks][3], h0, h1);
                mma_bf16(s[2 * ntp + 1], ql[ks][0], ql[ks][1], ql[ks][2], ql[ks][3], h2, h3);
                uint32_t e0, e1, e2, e3;
                LDSM_X4(e0, e1, e2, e3, kLoB + boff);
                mma_bf16(s[2 * ntp],     qh[ks][0], qh[ks][1], qh[ks][2], qh[ks][3], e0, e1);
                mma_bf16(s[2 * ntp + 1], qh[ks][0], qh[ks][1], qh[ks][2], qh[ks][3], e2, e3);
            }
        }

        // --- online softmax ---
        float mx0 = -1e30f, mx1 = -1e30f;
#pragma unroll
        for (int nt = 0; nt < 8; nt++) {
            mx0 = fmaxf(mx0, fmaxf(s[nt][0], s[nt][1]));
            mx1 = fmaxf(mx1, fmaxf(s[nt][2], s[nt][3]));
        }
        mx0 = fmaxf(mx0, __shfl_xor_sync(0xffffffffu, mx0, 1));
        mx0 = fmaxf(mx0, __shfl_xor_sync(0xffffffffu, mx0, 2));
        mx1 = fmaxf(mx1, __shfl_xor_sync(0xffffffffu, mx1, 1));
        mx1 = fmaxf(mx1, __shfl_xor_sync(0xffffffffu, mx1, 2));

        float mn0 = fmaxf(m0, mx0), mn1 = fmaxf(m1, mx1);
        float al0 = __expf(m0 - mn0), al1 = __expf(m1 - mn1);
        m0 = mn0; m1 = mn1;

        float sum0 = 0.f, sum1 = 0.f;
#pragma unroll
        for (int nt = 0; nt < 8; nt++) {
            s[nt][0] = __expf(s[nt][0] - mn0);
            s[nt][1] = __expf(s[nt][1] - mn0);
            s[nt][2] = __expf(s[nt][2] - mn1);
            s[nt][3] = __expf(s[nt][3] - mn1);
            sum0 += s[nt][0] + s[nt][1];
            sum1 += s[nt][2] + s[nt][3];
        }
        sum0 += __shfl_xor_sync(0xffffffffu, sum0, 1);
        sum0 += __shfl_xor_sync(0xffffffffu, sum0, 2);
        sum1 += __shfl_xor_sync(0xffffffffu, sum1, 1);
        sum1 += __shfl_xor_sync(0xffffffffu, sum1, 2);
        l0 = l0 * al0 + sum0;
        l1 = l1 * al1 + sum1;

#pragma unroll
        for (int nt = 0; nt < 8; nt++) {
            o[nt][0] *= al0; o[nt][1] *= al0;
            o[nt][2] *= al1; o[nt][3] *= al1;
        }

        // --- O += Phi Vhi + Plo Vhi + Phi Vlo ---
#pragma unroll
        for (int kt = 0; kt < 4; kt++) {
            uint32_t ph[4], pl[4];
            split_pack2(s[2 * kt][0],     s[2 * kt][1],     ph[0], pl[0]);
            split_pack2(s[2 * kt][2],     s[2 * kt][3],     ph[1], pl[1]);
            split_pack2(s[2 * kt + 1][0], s[2 * kt + 1][1], ph[2], pl[2]);
            split_pack2(s[2 * kt + 1][2], s[2 * kt + 1][3], ph[3], pl[3]);
#pragma unroll
            for (int ntp = 0; ntp < 4; ntp++) {
                const uint32_t voff = v4_off + kt * (16 * FPAD * 2) + ntp * 32;
                uint32_t vh0, vh1, vh2, vh3;
                LDSM_X4T(vh0, vh1, vh2, vh3, vHiB + voff);
                mma_bf16(o[2 * ntp],     ph[0], ph[1], ph[2], ph[3], vh0, vh1);
                mma_bf16(o[2 * ntp + 1], ph[0], ph[1], ph[2], ph[3], vh2, vh3);
                mma_bf16(o[2 * ntp],     pl[0], pl[1], pl[2], pl[3], vh0, vh1);
                mma_bf16(o[2 * ntp + 1], pl[0], pl[1], pl[2], pl[3], vh2, vh3);
                uint32_t vl0, vl1, vl2, vl3;
                LDSM_X4T(vl0, vl1, vl2, vl3, vLoB + voff);
                mma_bf16(o[2 * ntp],     ph[0], ph[1], ph[2], ph[3], vl0, vl1);
                mma_bf16(o[2 * ntp + 1], ph[0], ph[1], ph[2], ph[3], vl2, vl3);
            }
        }
        __syncthreads();
    }

    // Epilogue: normalize, store fp32
    const int r0 = qb + wid * 16 + (lane >> 2);
    float inv0 = 1.f / l0, inv1 = 1.f / l1;
    float* Orow = g_O + ((size_t)b * SEQ + r0) * EDIM + h * HDIM;
#pragma unroll
    for (int nt = 0; nt < 8; nt++) {
        int c = nt * 8 + (lane & 3) * 2;
        *(float2*)(Orow + c) = make_float2(o[nt][0] * inv0, o[nt][1] * inv0);
        *(float2*)(Orow + (size_t)8 * EDIM + c) = make_float2(o[nt][2] * inv1, o[nt][3] * inv1);
    }
}

// ---------------------------------------------------------------------------
// Launch
// ---------------------------------------------------------------------------
extern "C" void kernel_launch(void* const* d_in, const int* in_sizes, int n_in,
                              void* d_out, int out_size)
{
    (void)in_sizes; (void)n_in; (void)out_size;
    const float* q  = (const float*)d_in[0];
    const float* k  = (const float*)d_in[1];
    const float* v  = (const float*)d_in[2];
    const float* Wq = (const float*)d_in[3];
    const float* Wk = (const float*)d_in[4];
    const float* Wv = (const float*)d_in[5];
    const float* Wo = (const float*)d_in[6];
    float* out = (float*)d_out;

    __nv_bfloat16 *Qhi, *Qlo, *Khi, *Klo, *Vhi, *Vlo, *ahi, *alo, *whi, *wlo;
    float* Op;
    cudaGetSymbolAddress((void**)&Qhi, g_Qhi);
    cudaGetSymbolAddress((void**)&Qlo, g_Qlo);
    cudaGetSymbolAddress((void**)&Khi, g_Khi);
    cudaGetSymbolAddress((void**)&Klo, g_Klo);
    cudaGetSymbolAddress((void**)&Vhi, g_Vhi);
    cudaGetSymbolAddress((void**)&Vlo, g_Vlo);
    cudaGetSymbolAddress((void**)&ahi, g_ahi);
    cudaGetSymbolAddress((void**)&alo, g_alo);
    cudaGetSymbolAddress((void**)&whi, g_whi);
    cudaGetSymbolAddress((void**)&wlo, g_wlo);
    cudaGetSymbolAddress((void**)&Op, g_O);

    static int attr_set = 0;
    if (!attr_set) {
        cudaFuncSetAttribute(hgemm_pipe,
                             cudaFuncAttributeMaxDynamicSharedMemorySize, GSMEM_BYTES);
        cudaFuncSetAttribute(flash_hmma,
                             cudaFuncAttributeMaxDynamicSharedMemorySize, FSMEM_BYTES);
        attr_set = 1;
    }

    const int nA = MROWS * EDIM;   // 4M
    const int nW = EDIM * EDIM;    // 1M
    dim3 ggrid(EDIM / 128, MROWS / 128);   // (8, 32)

    // Q projection (epilogue pre-splits + pre-scales Q)
    split_bf16_kernel<<<nA / 1024, 256>>>(q, ahi, alo, nA);
    split_bf16_kernel<<<nW / 1024, 256>>>(Wq, whi, wlo, nW);
    hgemm_pipe<<<ggrid, 256, GSMEM_BYTES>>>(ahi, alo, whi, wlo, nullptr, Qhi, Qlo, QSCALE, MROWS, EDIM, EDIM);
    // K projection
    split_bf16_kernel<<<nA / 1024, 256>>>(k, ahi, alo, nA);
    split_bf16_kernel<<<nW / 1024, 256>>>(Wk, whi, wlo, nW);
    hgemm_pipe<<<ggrid, 256, GSMEM_BYTES>>>(ahi, alo, whi, wlo, nullptr, Khi, Klo, 1.0f, MROWS, EDIM, EDIM);
    // V projection
    split_bf16_kernel<<<nA / 1024, 256>>>(v, ahi, alo, nA);
    split_bf16_kernel<<<nW / 1024, 256>>>(Wv, whi, wlo, nW);
    hgemm_pipe<<<ggrid, 256, GSMEM_BYTES>>>(ahi, alo, whi, wlo, nullptr, Vhi, Vlo, 1.0f, MROWS, EDIM, EDIM);

    // Fused flash attention
    dim3 fgrid(SEQ / 128, NHEADS, BATCH);  // (16, 16, 2)
    flash_hmma<<<fgrid, 256, FSMEM_BYTES>>>();

    // Output projection (fp32 out)
    split_bf16_kernel<<<nA / 1024, 256>>>(Op, ahi, alo, nA);
    split_bf16_kernel<<<nW / 1024, 256>>>(Wo, whi, wlo, nW);
    hgemm_pipe<<<ggrid, 256, GSMEM_BYTES>>>(ahi, alo, whi, wlo, out, nullptr, nullptr, 1.0f, MROWS, EDIM, EDIM);
}

// round 6
// speedup vs baseline: 1.2324x; 1.0707x over previous
#include <cuda_runtime.h>
#include <cuda_bf16.h>
#include <cstdint>

// Problem constants
#define EDIM 1024
#define BATCH 2
#define SEQ 2048
#define NHEADS 16
#define HDIM 64
#define MROWS (BATCH * SEQ)          // 4096
#define QSCALE 0.125f                // 1/sqrt(64), exact power of two

// ---------------------------------------------------------------------------
// Scratch (allocation-free: static __device__ globals)
// ---------------------------------------------------------------------------
// Split inputs (dedicated per tensor -> no false serialization)
__device__ __nv_bfloat16 g_qsh[MROWS * EDIM], g_qsl[MROWS * EDIM];
__device__ __nv_bfloat16 g_ksh[MROWS * EDIM], g_ksl[MROWS * EDIM];
__device__ __nv_bfloat16 g_vsh[MROWS * EDIM], g_vsl[MROWS * EDIM];
__device__ __nv_bfloat16 g_wqh[EDIM * EDIM], g_wql[EDIM * EDIM];
__device__ __nv_bfloat16 g_wkh[EDIM * EDIM], g_wkl[EDIM * EDIM];
__device__ __nv_bfloat16 g_wvh[EDIM * EDIM], g_wvl[EDIM * EDIM];
__device__ __nv_bfloat16 g_woh[EDIM * EDIM], g_wol[EDIM * EDIM];
// Projected Q/K/V (pre-split, Q pre-scaled)
__device__ __nv_bfloat16 g_Qhi[MROWS * EDIM], g_Qlo[MROWS * EDIM];
__device__ __nv_bfloat16 g_Khi[MROWS * EDIM], g_Klo[MROWS * EDIM];
__device__ __nv_bfloat16 g_Vhi[MROWS * EDIM], g_Vlo[MROWS * EDIM];
// Attention output (fp32) and its split
__device__ float g_O[MROWS * EDIM];
__device__ __nv_bfloat16 g_Ohi[MROWS * EDIM], g_Olo[MROWS * EDIM];

// ---------------------------------------------------------------------------
// Primitives
// ---------------------------------------------------------------------------
__device__ __forceinline__ uint32_t smem_u32(const void* p) {
    uint32_t a;
    asm("{ .reg .u64 t; cvta.to.shared.u64 t, %1; cvt.u32.u64 %0, t; }"
        : "=r"(a) : "l"(p));
    return a;
}

#define LDSM_X4(r0, r1, r2, r3, addr) \
    asm volatile("ldmatrix.sync.aligned.m8n8.x4.shared.b16 {%0,%1,%2,%3}, [%4];" \
        : "=r"(r0), "=r"(r1), "=r"(r2), "=r"(r3) : "r"(addr))

#define LDSM_X4T(r0, r1, r2, r3, addr) \
    asm volatile("ldmatrix.sync.aligned.m8n8.x4.trans.shared.b16 {%0,%1,%2,%3}, [%4];" \
        : "=r"(r0), "=r"(r1), "=r"(r2), "=r"(r3) : "r"(addr))

#define CP_ASYNC16(saddr, gptr) \
    asm volatile("cp.async.cg.shared.global [%0], [%1], 16;" \
        :: "r"(saddr), "l"(gptr))

#define CP_COMMIT() asm volatile("cp.async.commit_group;" ::: "memory")
#define CP_WAIT1()  asm volatile("cp.async.wait_group 1;" ::: "memory")
#define CP_WAIT0()  asm volatile("cp.async.wait_group 0;" ::: "memory")

__device__ __forceinline__ void mma_bf16(float* c, uint32_t a0, uint32_t a1,
                                         uint32_t a2, uint32_t a3,
                                         uint32_t b0, uint32_t b1) {
    asm volatile(
        "mma.sync.aligned.m16n8k16.row.col.f32.bf16.bf16.f32 "
        "{%0,%1,%2,%3}, {%4,%5,%6,%7}, {%8,%9}, {%0,%1,%2,%3};"
        : "+f"(c[0]), "+f"(c[1]), "+f"(c[2]), "+f"(c[3])
        : "r"(a0), "r"(a1), "r"(a2), "r"(a3), "r"(b0), "r"(b1));
}

__device__ __forceinline__ uint32_t pack_bf16(float x, float y) {
    __nv_bfloat162 t = __floats2bfloat162_rn(x, y);
    return *(uint32_t*)&t;
}

__device__ __forceinline__ void split_pack2(float x, float y,
                                            uint32_t& hi, uint32_t& lo) {
    __nv_bfloat16 hx = __float2bfloat16(x);
    __nv_bfloat16 hy = __float2bfloat16(y);
    __nv_bfloat162 h2 = __halves2bfloat162(hx, hy);
    hi = *(uint32_t*)&h2;
    lo = pack_bf16(x - __bfloat162float(hx), y - __bfloat162float(hy));
}

// ---------------------------------------------------------------------------
// Splits
// ---------------------------------------------------------------------------
__device__ __forceinline__ void split_body(
    const float* __restrict__ x, __nv_bfloat16* __restrict__ hi,
    __nv_bfloat16* __restrict__ lo, int n, int bx)
{
    int i = (bx * 256 + threadIdx.x) * 4;
    if (i >= n) return;
    float4 v = *(const float4*)(x + i);
    uint32_t h01, l01, h23, l23;
    split_pack2(v.x, v.y, h01, l01);
    split_pack2(v.z, v.w, h23, l23);
    *(uint2*)(hi + i) = make_uint2(h01, h23);
    *(uint2*)(lo + i) = make_uint2(l01, l23);
}

__global__ __launch_bounds__(256) void split_bf16_kernel(
    const float* __restrict__ x, __nv_bfloat16* __restrict__ hi,
    __nv_bfloat16* __restrict__ lo, int n)
{
    split_body(x, hi, lo, n, blockIdx.x);
}

// One kernel splits all 7 inputs. blockIdx.y selects the tensor.
__global__ __launch_bounds__(256) void split_all_kernel(
    const float* q, const float* k, const float* v,
    const float* wq, const float* wk, const float* wv, const float* wo)
{
    const int nA = MROWS * EDIM, nW = EDIM * EDIM;
    switch (blockIdx.y) {
        case 0: split_body(q,  g_qsh, g_qsl, nA, blockIdx.x); break;
        case 1: split_body(k,  g_ksh, g_ksl, nA, blockIdx.x); break;
        case 2: split_body(v,  g_vsh, g_vsl, nA, blockIdx.x); break;
        case 3: split_body(wq, g_wqh, g_wql, nW, blockIdx.x); break;
        case 4: split_body(wk, g_wkh, g_wkl, nW, blockIdx.x); break;
        case 5: split_body(wv, g_wvh, g_wvl, nW, blockIdx.x); break;
        case 6: split_body(wo, g_woh, g_wol, nW, blockIdx.x); break;
    }
}

// ---------------------------------------------------------------------------
// Pipelined HMMA bf16x3 GEMM: C = Ahi Whi^T + Alo Whi^T + Ahi Wlo^T
// CTA 128x128, BK=32, 2-stage cp.async, 8 warps (64x32 each), 2 CTAs/SM.
// ---------------------------------------------------------------------------
#define GPAD 40
#define GT_BYTES (128 * GPAD * 2)        // 10240 per tile
#define GSMEM_BYTES (8 * GT_BYTES)       // 2 stages x 4 tiles = 81920

__global__ __launch_bounds__(256, 2) void hgemm_pipe(
    const __nv_bfloat16* __restrict__ Ahi, const __nv_bfloat16* __restrict__ Alo,
    const __nv_bfloat16* __restrict__ Whi, const __nv_bfloat16* __restrict__ Wlo,
    float* __restrict__ Cf,
    __nv_bfloat16* __restrict__ Chi, __nv_bfloat16* __restrict__ Clo,
    float scale, int M, int N, int K)
{
    extern __shared__ __nv_bfloat16 hsm[];
    const uint32_t sb = smem_u32(hsm);

    const int tid = threadIdx.x;
    const int wid = tid >> 5;
    const int lane = tid & 31;
    const int bm = blockIdx.y * 128;
    const int bn = blockIdx.x * 128;
    const int moff = (wid >> 2) * 64;
    const int noff = (wid & 3) * 32;

    const int lr = tid >> 2;            // 0..63
    const int lc = (tid & 3) * 8;       // 0,8,16,24
    const size_t gA0 = (size_t)(bm + lr) * K + lc;
    const size_t gW0 = (size_t)(bn + lr) * K + lc;
    const uint32_t sOff0 = (uint32_t)(lr * GPAD + lc) * 2;
    const uint32_t sOff1 = (uint32_t)((lr + 64) * GPAD + lc) * 2;

    float acc[4][4][4];
#pragma unroll
    for (int mt = 0; mt < 4; mt++)
#pragma unroll
        for (int nt = 0; nt < 4; nt++)
#pragma unroll
            for (int r = 0; r < 4; r++) acc[mt][nt][r] = 0.f;

    const uint32_t a_off = ((moff + (lane & 15)) * GPAD + (lane >> 4) * 8) * 2;
    const uint32_t b4_off =
        ((noff + ((lane >> 4) & 1) * 8 + (lane & 7)) * GPAD + ((lane >> 3) & 1) * 8) * 2;

    const int NT = K / 32;

    auto load_stage = [&](int t) {
        const int s = t & 1;
        const int k0 = t * 32;
        const uint32_t s0 = sb + s * 4 * GT_BYTES;
        const __nv_bfloat16* g;
        g = Ahi + gA0 + k0;
        CP_ASYNC16(s0 + 0 * GT_BYTES + sOff0, g);
        CP_ASYNC16(s0 + 0 * GT_BYTES + sOff1, g + (size_t)64 * K);
        g = Alo + gA0 + k0;
        CP_ASYNC16(s0 + 1 * GT_BYTES + sOff0, g);
        CP_ASYNC16(s0 + 1 * GT_BYTES + sOff1, g + (size_t)64 * K);
        g = Whi + gW0 + k0;
        CP_ASYNC16(s0 + 2 * GT_BYTES + sOff0, g);
        CP_ASYNC16(s0 + 2 * GT_BYTES + sOff1, g + (size_t)64 * K);
        g = Wlo + gW0 + k0;
        CP_ASYNC16(s0 + 3 * GT_BYTES + sOff0, g);
        CP_ASYNC16(s0 + 3 * GT_BYTES + sOff1, g + (size_t)64 * K);
    };

    load_stage(0);
    CP_COMMIT();

    for (int t = 0; t < NT; t++) {
        if (t + 1 < NT) {
            load_stage(t + 1);
            CP_COMMIT();
            CP_WAIT1();
        } else {
            CP_WAIT0();
        }
        __syncthreads();

        const uint32_t s0 = sb + (t & 1) * 4 * GT_BYTES;
        const uint32_t aHiB = s0;
        const uint32_t aLoB = s0 + GT_BYTES;
        const uint32_t wHiB = s0 + 2 * GT_BYTES;
        const uint32_t wLoB = s0 + 3 * GT_BYTES;

#pragma unroll
        for (int ks = 0; ks < 2; ks++) {
            const uint32_t koff = ks * 32;
            uint32_t bhi[4][2], blo[4][2];
#pragma unroll
            for (int ntp = 0; ntp < 2; ntp++) {
                const uint32_t boff = b4_off + ntp * (16 * GPAD * 2) + koff;
                LDSM_X4(bhi[2 * ntp][0], bhi[2 * ntp][1],
                        bhi[2 * ntp + 1][0], bhi[2 * ntp + 1][1], wHiB + boff);
                LDSM_X4(blo[2 * ntp][0], blo[2 * ntp][1],
                        blo[2 * ntp + 1][0], blo[2 * ntp + 1][1], wLoB + boff);
            }
#pragma unroll
            for (int mt = 0; mt < 4; mt++) {
                uint32_t ah0, ah1, ah2, ah3, al0, al1, al2, al3;
                LDSM_X4(ah0, ah1, ah2, ah3, aHiB + a_off + mt * (16 * GPAD * 2) + koff);
                LDSM_X4(al0, al1, al2, al3, aLoB + a_off + mt * (16 * GPAD * 2) + koff);
#pragma unroll
                for (int nt = 0; nt < 4; nt++) {
                    mma_bf16(acc[mt][nt], ah0, ah1, ah2, ah3, bhi[nt][0], bhi[nt][1]);
                    mma_bf16(acc[mt][nt], al0, al1, al2, al3, bhi[nt][0], bhi[nt][1]);
                    mma_bf16(acc[mt][nt], ah0, ah1, ah2, ah3, blo[nt][0], blo[nt][1]);
                }
            }
        }
        __syncthreads();
    }

    // Epilogue
    if (Cf) {
#pragma unroll
        for (int mt = 0; mt < 4; mt++)
#pragma unroll
            for (int nt = 0; nt < 4; nt++) {
                int r0 = bm + moff + mt * 16 + (lane >> 2);
                int c0 = bn + noff + nt * 8 + (lane & 3) * 2;
                *(float2*)(Cf + (size_t)r0 * N + c0) = make_float2(acc[mt][nt][0], acc[mt][nt][1]);
                *(float2*)(Cf + (size_t)(r0 + 8) * N + c0) = make_float2(acc[mt][nt][2], acc[mt][nt][3]);
            }
    } else {
#pragma unroll
        for (int mt = 0; mt < 4; mt++)
#pragma unroll
            for (int nt = 0; nt < 4; nt++) {
                int r0 = bm + moff + mt * 16 + (lane >> 2);
                int c0 = bn + noff + nt * 8 + (lane & 3) * 2;
                uint32_t h, l;
                split_pack2(acc[mt][nt][0] * scale, acc[mt][nt][1] * scale, h, l);
                *(uint32_t*)(Chi + (size_t)r0 * N + c0) = h;
                *(uint32_t*)(Clo + (size_t)r0 * N + c0) = l;
                split_pack2(acc[mt][nt][2] * scale, acc[mt][nt][3] * scale, h, l);
                *(uint32_t*)(Chi + (size_t)(r0 + 8) * N + c0) = h;
                *(uint32_t*)(Clo + (size_t)(r0 + 8) * N + c0) = l;
            }
    }
}

// ---------------------------------------------------------------------------
// Flash attention on HMMA, 3-stage cp.async KV ring, ONE sync per iteration.
// CTA: 128 q-rows of one (b,h); 8 warps; warp = 16 q-rows x 64-kv stage.
// ---------------------------------------------------------------------------
#define FPAD 72
#define FQ_BYTES (128 * FPAD * 2)        // 18432 per Q tile
#define FKV_BYTES (64 * FPAD * 2)        // 9216 per KV tile
#define FSMEM_BYTES (2 * FQ_BYTES + 3 * 4 * FKV_BYTES)   // 147456

__global__ __launch_bounds__(256) void flash_hmma()
{
    extern __shared__ __nv_bfloat16 fsm[];
    const uint32_t sb = smem_u32(fsm);
    const uint32_t qHiB = sb;
    const uint32_t qLoB = sb + FQ_BYTES;
    const uint32_t kvB = sb + 2 * FQ_BYTES;   // + (t%3)*4*FKV + tile*FKV

    const int tid = threadIdx.x;
    const int wid = tid >> 5;
    const int lane = tid & 31;
    const int qb = blockIdx.x * 128;
    const int h = blockIdx.y;
    const int b = blockIdx.z;

    const size_t qbase = ((size_t)b * SEQ + qb) * EDIM + h * HDIM;
    const size_t kvbase = (size_t)b * SEQ * EDIM + h * HDIM;

    // Q tiles -> smem
#pragma unroll
    for (int it = 0; it < 4; it++) {
        int l = it * 256 + tid;
        int r = l >> 3;
        int c = (l & 7) * 8;
        *(uint4*)(fsm + r * FPAD + c) = *(const uint4*)(g_Qhi + qbase + (size_t)r * EDIM + c);
        *(uint4*)(fsm + 128 * FPAD + r * FPAD + c) = *(const uint4*)(g_Qlo + qbase + (size_t)r * EDIM + c);
    }

    // KV stage loaders
    const int lr = tid >> 3;            // 0..31
    const int lc = (tid & 7) * 8;       // 0..56
    const size_t gKV0 = kvbase + (size_t)lr * EDIM + lc;
    const uint32_t sKV0 = (uint32_t)(lr * FPAD + lc) * 2;
    const uint32_t sKV1 = (uint32_t)((lr + 32) * FPAD + lc) * 2;

    auto load_stage = [&](int t) {
        const uint32_t s0 = kvB + (t % 3) * 4 * FKV_BYTES;
        const size_t g0 = gKV0 + (size_t)t * 64 * EDIM;
        CP_ASYNC16(s0 + 0 * FKV_BYTES + sKV0, g_Khi + g0);
        CP_ASYNC16(s0 + 0 * FKV_BYTES + sKV1, g_Khi + g0 + (size_t)32 * EDIM);
        CP_ASYNC16(s0 + 1 * FKV_BYTES + sKV0, g_Klo + g0);
        CP_ASYNC16(s0 + 1 * FKV_BYTES + sKV1, g_Klo + g0 + (size_t)32 * EDIM);
        CP_ASYNC16(s0 + 2 * FKV_BYTES + sKV0, g_Vhi + g0);
        CP_ASYNC16(s0 + 2 * FKV_BYTES + sKV1, g_Vhi + g0 + (size_t)32 * EDIM);
        CP_ASYNC16(s0 + 3 * FKV_BYTES + sKV0, g_Vlo + g0);
        CP_ASYNC16(s0 + 3 * FKV_BYTES + sKV1, g_Vlo + g0 + (size_t)32 * EDIM);
    };

    load_stage(0);
    CP_COMMIT();
    load_stage(1);
    CP_COMMIT();
    __syncthreads();   // publish Q smem stores

    // Hoist Q fragments (invariant over KV loop)
    const uint32_t a_off = ((wid * 16 + (lane & 15)) * FPAD + (lane >> 4) * 8) * 2;
    uint32_t qh[4][4], ql[4][4];
#pragma unroll
    for (int ks = 0; ks < 4; ks++) {
        LDSM_X4(qh[ks][0], qh[ks][1], qh[ks][2], qh[ks][3], qHiB + a_off + ks * 32);
        LDSM_X4(ql[ks][0], ql[ks][1], ql[ks][2], ql[ks][3], qLoB + a_off + ks * 32);
    }

    const uint32_t k4_off =
        ((((lane >> 4) & 1) * 8 + (lane & 7)) * FPAD + ((lane >> 3) & 1) * 8) * 2;
    const uint32_t v4_off =
        (((lane & 7) + ((lane >> 3) & 1) * 8) * FPAD + ((lane >> 4) & 1) * 8) * 2;

    float o[8][4];
#pragma unroll
    for (int nt = 0; nt < 8; nt++)
#pragma unroll
        for (int r = 0; r < 4; r++) o[nt][r] = 0.f;
    float m0 = -1e30f, m1 = -1e30f, l0 = 0.f, l1 = 0.f;

    const int NT = SEQ / 64;   // 32

    for (int t = 0; t < NT; t++) {
        if (t + 1 < NT) CP_WAIT1(); else CP_WAIT0();
        __syncthreads();   // publish stage t to all warps; bounds skew

        const uint32_t s0 = kvB + (t % 3) * 4 * FKV_BYTES;
        const uint32_t kHiB = s0;
        const uint32_t kLoB = s0 + FKV_BYTES;
        const uint32_t vHiB = s0 + 2 * FKV_BYTES;
        const uint32_t vLoB = s0 + 3 * FKV_BYTES;

        // --- S = Qhi Khi^T + Qlo Khi^T + Qhi Klo^T ---
        float s[8][4];
#pragma unroll
        for (int nt = 0; nt < 8; nt++)
#pragma unroll
            for (int r = 0; r < 4; r++) s[nt][r] = 0.f;

#pragma unroll
        for (int ks = 0; ks < 4; ks++) {
            const uint32_t koff = ks * 32;
#pragma unroll
            for (int ntp = 0; ntp < 4; ntp++) {
                const uint32_t boff = k4_off + ntp * (16 * FPAD * 2) + koff;
                uint32_t h0, h1, h2, h3;
                LDSM_X4(h0, h1, h2, h3, kHiB + boff);
                mma_bf16(s[2 * ntp],     qh[ks][0], qh[ks][1], qh[ks][2], qh[ks][3], h0, h1);
                mma_bf16(s[2 * ntp + 1], qh[ks][0], qh[ks][1], qh[ks][2], qh[ks][3], h2, h3);
                mma_bf16(s[2 * ntp],     ql[ks][0], ql[ks][1], ql[ks][2], ql[ks][3], h0, h1);
                mma_bf16(s[2 * ntp + 1], ql[ks][0], ql[ks][1], ql[ks][2], ql[ks][3], h2, h3);
                uint32_t e0, e1, e2, e3;
                LDSM_X4(e0, e1, e2, e3, kLoB + boff);
                mma_bf16(s[2 * ntp],     qh[ks][0], qh[ks][1], qh[ks][2], qh[ks][3], e0, e1);
                mma_bf16(s[2 * ntp + 1], qh[ks][0], qh[ks][1], qh[ks][2], qh[ks][3], e2, e3);
            }
        }

        // --- online softmax ---
        float mx0 = -1e30f, mx1 = -1e30f;
#pragma unroll
        for (int nt = 0; nt < 8; nt++) {
            mx0 = fmaxf(mx0, fmaxf(s[nt][0], s[nt][1]));
            mx1 = fmaxf(mx1, fmaxf(s[nt][2], s[nt][3]));
        }
        mx0 = fmaxf(mx0, __shfl_xor_sync(0xffffffffu, mx0, 1));
        mx0 = fmaxf(mx0, __shfl_xor_sync(0xffffffffu, mx0, 2));
        mx1 = fmaxf(mx1, __shfl_xor_sync(0xffffffffu, mx1, 1));
        mx1 = fmaxf(mx1, __shfl_xor_sync(0xffffffffu, mx1, 2));

        float mn0 = fmaxf(m0, mx0), mn1 = fmaxf(m1, mx1);
        float al0 = __expf(m0 - mn0), al1 = __expf(m1 - mn1);
        m0 = mn0; m1 = mn1;

        float sum0 = 0.f, sum1 = 0.f;
#pragma unroll
        for (int nt = 0; nt < 8; nt++) {
            s[nt][0] = __expf(s[nt][0] - mn0);
            s[nt][1] = __expf(s[nt][1] - mn0);
            s[nt][2] = __expf(s[nt][2] - mn1);
            s[nt][3] = __expf(s[nt][3] - mn1);
            sum0 += s[nt][0] + s[nt][1];
            sum1 += s[nt][2] + s[nt][3];
        }
        sum0 += __shfl_xor_sync(0xffffffffu, sum0, 1);
        sum0 += __shfl_xor_sync(0xffffffffu, sum0, 2);
        sum1 += __shfl_xor_sync(0xffffffffu, sum1, 1);
        sum1 += __shfl_xor_sync(0xffffffffu, sum1, 2);
        l0 = l0 * al0 + sum0;
        l1 = l1 * al1 + sum1;

#pragma unroll
        for (int nt = 0; nt < 8; nt++) {
            o[nt][0] *= al0; o[nt][1] *= al0;
            o[nt][2] *= al1; o[nt][3] *= al1;
        }

        // --- O += Phi Vhi + Plo Vhi + Phi Vlo ---
#pragma unroll
        for (int kt = 0; kt < 4; kt++) {
            uint32_t ph[4], pl[4];
            split_pack2(s[2 * kt][0],     s[2 * kt][1],     ph[0], pl[0]);
            split_pack2(s[2 * kt][2],     s[2 * kt][3],     ph[1], pl[1]);
            split_pack2(s[2 * kt + 1][0], s[2 * kt + 1][1], ph[2], pl[2]);
            split_pack2(s[2 * kt + 1][2], s[2 * kt + 1][3], ph[3], pl[3]);
#pragma unroll
            for (int ntp = 0; ntp < 4; ntp++) {
                const uint32_t voff = v4_off + kt * (16 * FPAD * 2) + ntp * 32;
                uint32_t vh0, vh1, vh2, vh3;
                LDSM_X4T(vh0, vh1, vh2, vh3, vHiB + voff);
                mma_bf16(o[2 * ntp],     ph[0], ph[1], ph[2], ph[3], vh0, vh1);
                mma_bf16(o[2 * ntp + 1], ph[0], ph[1], ph[2], ph[3], vh2, vh3);
                mma_bf16(o[2 * ntp],     pl[0], pl[1], pl[2], pl[3], vh0, vh1);
                mma_bf16(o[2 * ntp + 1], pl[0], pl[1], pl[2], pl[3], vh2, vh3);
                uint32_t vl0, vl1, vl2, vl3;
                LDSM_X4T(vl0, vl1, vl2, vl3, vLoB + voff);
                mma_bf16(o[2 * ntp],     ph[0], ph[1], ph[2], ph[3], vl0, vl1);
                mma_bf16(o[2 * ntp + 1], ph[0], ph[1], ph[2], ph[3], vl2, vl3);
            }
        }

        // Tail-issue load for t+2 into stage (t+2)%3 — never collides with
        // readers of stage t%3; stragglers in compute(t) are unaffected.
        if (t + 2 < NT) {
            load_stage(t + 2);
            CP_COMMIT();
        }
    }

    // Epilogue: normalize, store fp32
    const int r0 = qb + wid * 16 + (lane >> 2);
    float inv0 = 1.f / l0, inv1 = 1.f / l1;
    float* Orow = g_O + ((size_t)b * SEQ + r0) * EDIM + h * HDIM;
#pragma unroll
    for (int nt = 0; nt < 8; nt++) {
        int c = nt * 8 + (lane & 3) * 2;
        *(float2*)(Orow + c) = make_float2(o[nt][0] * inv0, o[nt][1] * inv0);
        *(float2*)(Orow + (size_t)8 * EDIM + c) = make_float2(o[nt][2] * inv1, o[nt][3] * inv1);
    }
}

// ---------------------------------------------------------------------------
// Launch: 7 kernels total
// ---------------------------------------------------------------------------
extern "C" void kernel_launch(void* const* d_in, const int* in_sizes, int n_in,
                              void* d_out, int out_size)
{
    (void)in_sizes; (void)n_in; (void)out_size;
    const float* q  = (const float*)d_in[0];
    const float* k  = (const float*)d_in[1];
    const float* v  = (const float*)d_in[2];
    const float* Wq = (const float*)d_in[3];
    const float* Wk = (const float*)d_in[4];
    const float* Wv = (const float*)d_in[5];
    const float* Wo = (const float*)d_in[6];
    float* out = (float*)d_out;

    __nv_bfloat16 *qsh, *qsl, *ksh, *ksl, *vsh, *vsl;
    __nv_bfloat16 *wqh, *wql, *wkh, *wkl, *wvh, *wvl, *woh, *wol;
    __nv_bfloat16 *Qhi, *Qlo, *Khi, *Klo, *Vhi, *Vlo, *Ohi, *Olo;
    float* Op;
    cudaGetSymbolAddress((void**)&qsh, g_qsh); cudaGetSymbolAddress((void**)&qsl, g_qsl);
    cudaGetSymbolAddress((void**)&ksh, g_ksh); cudaGetSymbolAddress((void**)&ksl, g_ksl);
    cudaGetSymbolAddress((void**)&vsh, g_vsh); cudaGetSymbolAddress((void**)&vsl, g_vsl);
    cudaGetSymbolAddress((void**)&wqh, g_wqh); cudaGetSymbolAddress((void**)&wql, g_wql);
    cudaGetSymbolAddress((void**)&wkh, g_wkh); cudaGetSymbolAddress((void**)&wkl, g_wkl);
    cudaGetSymbolAddress((void**)&wvh, g_wvh); cudaGetSymbolAddress((void**)&wvl, g_wvl);
    cudaGetSymbolAddress((void**)&woh, g_woh); cudaGetSymbolAddress((void**)&wol, g_wol);
    cudaGetSymbolAddress((void**)&Qhi, g_Qhi); cudaGetSymbolAddress((void**)&Qlo, g_Qlo);
    cudaGetSymbolAddress((void**)&Khi, g_Khi); cudaGetSymbolAddress((void**)&Klo, g_Klo);
    cudaGetSymbolAddress((void**)&Vhi, g_Vhi); cudaGetSymbolAddress((void**)&Vlo, g_Vlo);
    cudaGetSymbolAddress((void**)&Ohi, g_Ohi); cudaGetSymbolAddress((void**)&Olo, g_Olo);
    cudaGetSymbolAddress((void**)&Op, g_O);

    static int attr_set = 0;
    if (!attr_set) {
        cudaFuncSetAttribute(hgemm_pipe,
                             cudaFuncAttributeMaxDynamicSharedMemorySize, GSMEM_BYTES);
        cudaFuncSetAttribute(flash_hmma,
                             cudaFuncAttributeMaxDynamicSharedMemorySize, FSMEM_BYTES);
        attr_set = 1;
    }

    const int nA = MROWS * EDIM;   // 4M
    dim3 ggrid(EDIM / 128, MROWS / 128);   // (8, 32)

    // 1) Split all 7 inputs in one kernel
    dim3 sgrid(nA / 1024, 7);
    split_all_kernel<<<sgrid, 256>>>(q, k, v, Wq, Wk, Wv, Wo);

    // 2-4) Projections (epilogues pre-split; Q pre-scaled)
    hgemm_pipe<<<ggrid, 256, GSMEM_BYTES>>>(qsh, qsl, wqh, wql, nullptr, Qhi, Qlo, QSCALE, MROWS, EDIM, EDIM);
    hgemm_pipe<<<ggrid, 256, GSMEM_BYTES>>>(ksh, ksl, wkh, wkl, nullptr, Khi, Klo, 1.0f, MROWS, EDIM, EDIM);
    hgemm_pipe<<<ggrid, 256, GSMEM_BYTES>>>(vsh, vsl, wvh, wvl, nullptr, Vhi, Vlo, 1.0f, MROWS, EDIM, EDIM);

    // 5) Fused flash attention
    dim3 fgrid(SEQ / 128, NHEADS, BATCH);  // (16, 16, 2)
    flash_hmma<<<fgrid, 256, FSMEM_BYTES>>>();

    // 6) Split O, 7) output projection (fp32 out)
    split_bf16_kernel<<<nA / 1024, 256>>>(Op, Ohi, Olo, nA);
    hgemm_pipe<<<ggrid, 256, GSMEM_BYTES>>>(Ohi, Olo, woh, wol, out, nullptr, nullptr, 1.0f, MROWS, EDIM, EDIM);
}